// round 3
// baseline (speedup 1.0000x reference)
#include <cuda_runtime.h>
#include <math.h>

// Problem constants
#define BB 16
#define LL 512
#define FF 384
#define HH 384
#define KW 3
#define MAX_OUT 4096
#define MROWS (BB * LL)        // 8192
#define KDIM (KW * FF)         // 1152

// Scratch (static device allocations — allowed)
__device__ float g_W1t[KDIM * HH];
__device__ float g_W2t[KDIM * FF];
__device__ float g_buf1[MROWS * HH];
__device__ float g_buf2[MROWS * HH];
__device__ int   g_ends[BB * LL];

// ---------------------------------------------------------------------------
// Weight transpose: W[h, f, k] -> Wt[kk = k*FF + f, h]
// ---------------------------------------------------------------------------
__global__ void transpose_w_kernel(const float* __restrict__ w1,
                                   const float* __restrict__ w2) {
    int o = blockIdx.x * 256 + threadIdx.x;
    if (o >= KDIM * HH) return;
    int kk = o / HH;
    int h = o - kk * HH;
    int k = kk / FF;
    int f = kk - k * FF;
    g_W1t[o] = w1[h * KDIM + f * KW + k];
    g_W2t[o] = w2[h * KDIM + f * KW + k];
}

// ---------------------------------------------------------------------------
// Implicit-im2col GEMM: C[m, n] = sum_kk A(m, kk) * Bt[kk, n] + bias[n]
//   A(m, kk): m=b*512+l ; kk=k*384+f ; value = X[b, l+k-1, f] (0 outside)
// BM=128, BN=128, BK=16, 256 threads, 8x8 microtile
// ---------------------------------------------------------------------------
__global__ void __launch_bounds__(256, 2)
conv_gemm_kernel(const float* __restrict__ A,
                 const float* __restrict__ Bt,
                 const float* __restrict__ bias,
                 float* __restrict__ C) {
    __shared__ float As[16][132];   // [kk_local][m_local], padded
    __shared__ float Bs[16][128];   // [kk_local][n_local]

    const int bn = blockIdx.x * 128;
    const int bm = blockIdx.y * 128;
    const int tid = threadIdx.x;
    const int tx = tid & 15;
    const int ty = tid >> 4;

    float acc[8][8];
#pragma unroll
    for (int i = 0; i < 8; ++i)
#pragma unroll
        for (int j = 0; j < 8; ++j) acc[i][j] = 0.f;

    const int a_kk = tid & 15;      // kk_local
    const int a_m0 = tid >> 4;      // first m_local (stride 16)

    for (int k0 = 0; k0 < KDIM; k0 += 16) {
        // ---- load A tile (chunk of 16 kk never straddles a k boundary: 384%16==0)
        int kk = k0 + a_kk;
        int k = kk / FF;
        int f = kk - k * FF;
#pragma unroll
        for (int j = 0; j < 8; ++j) {
            int ml = a_m0 + j * 16;
            int m = bm + ml;
            int l = (m & (LL - 1)) + k - 1;
            float v = 0.f;
            if ((unsigned)l < (unsigned)LL)
                v = __ldg(&A[((m & ~(LL - 1)) + l) * FF + f]);
            As[a_kk][ml] = v;
        }
        // ---- load B tile (float4, fully coalesced)
        {
            int i0 = tid;
            float4 v0 = *(const float4*)&Bt[(k0 + (i0 >> 5)) * HH + bn + ((i0 & 31) << 2)];
            *(float4*)&Bs[i0 >> 5][(i0 & 31) << 2] = v0;
            int i1 = tid + 256;
            float4 v1 = *(const float4*)&Bt[(k0 + (i1 >> 5)) * HH + bn + ((i1 & 31) << 2)];
            *(float4*)&Bs[i1 >> 5][(i1 & 31) << 2] = v1;
        }
        __syncthreads();
#pragma unroll
        for (int kk2 = 0; kk2 < 16; ++kk2) {
            float a[8], b[8];
#pragma unroll
            for (int i = 0; i < 8; ++i) a[i] = As[kk2][ty * 8 + i];
#pragma unroll
            for (int j = 0; j < 8; ++j) b[j] = Bs[kk2][tx * 8 + j];
#pragma unroll
            for (int i = 0; i < 8; ++i)
#pragma unroll
                for (int j = 0; j < 8; ++j) acc[i][j] += a[i] * b[j];
        }
        __syncthreads();
    }

#pragma unroll
    for (int i = 0; i < 8; ++i) {
        int m = bm + ty * 8 + i;
#pragma unroll
        for (int j4 = 0; j4 < 2; ++j4) {
            int n = bn + tx * 8 + j4 * 4;
            float4 o;
            o.x = acc[i][j4 * 4 + 0] + __ldg(&bias[n + 0]);
            o.y = acc[i][j4 * 4 + 1] + __ldg(&bias[n + 1]);
            o.z = acc[i][j4 * 4 + 2] + __ldg(&bias[n + 2]);
            o.w = acc[i][j4 * 4 + 3] + __ldg(&bias[n + 3]);
            *(float4*)&C[m * HH + n] = o;
        }
    }
}

// ---------------------------------------------------------------------------
// LayerNorm(384) + ReLU, one block (128 thr) per row
// ---------------------------------------------------------------------------
__global__ void ln_relu_kernel(const float* __restrict__ X,
                               const float* __restrict__ g,
                               const float* __restrict__ b,
                               float* __restrict__ Y) {
    __shared__ float shs[4], shss[4];
    int row = blockIdx.x;
    int t = threadIdx.x;
    const float* x = X + row * 384;
    float v0 = x[t], v1 = x[t + 128], v2 = x[t + 256];
    float s = v0 + v1 + v2;
    float ss = v0 * v0 + v1 * v1 + v2 * v2;
#pragma unroll
    for (int o = 16; o; o >>= 1) {
        s += __shfl_down_sync(0xffffffffu, s, o);
        ss += __shfl_down_sync(0xffffffffu, ss, o);
    }
    int w = t >> 5;
    if ((t & 31) == 0) { shs[w] = s; shss[w] = ss; }
    __syncthreads();
    float ts = shs[0] + shs[1] + shs[2] + shs[3];
    float tss = shss[0] + shss[1] + shss[2] + shss[3];
    float mu = ts * (1.f / 384.f);
    float var = tss * (1.f / 384.f) - mu * mu;
    float inv = rsqrtf(var + 1e-5f);
    float* y = Y + row * 384;
    y[t]       = fmaxf((v0 - mu) * inv * __ldg(&g[t])       + __ldg(&b[t]), 0.f);
    y[t + 128] = fmaxf((v1 - mu) * inv * __ldg(&g[t + 128]) + __ldg(&b[t + 128]), 0.f);
    y[t + 256] = fmaxf((v2 - mu) * inv * __ldg(&g[t + 256]) + __ldg(&b[t + 256]), 0.f);
}

// ---------------------------------------------------------------------------
// LayerNorm(384) + ReLU + dot(lin_w) + lin_b + ReLU + exp -> durations[row]
// ---------------------------------------------------------------------------
__global__ void ln_dur_kernel(const float* __restrict__ X,
                              const float* __restrict__ g,
                              const float* __restrict__ b,
                              const float* __restrict__ lw,
                              const float* __restrict__ lb,
                              float* __restrict__ dur) {
    __shared__ float shs[4], shss[4];
    int row = blockIdx.x;
    int t = threadIdx.x;
    const float* x = X + row * 384;
    float v0 = x[t], v1 = x[t + 128], v2 = x[t + 256];
    float s = v0 + v1 + v2;
    float ss = v0 * v0 + v1 * v1 + v2 * v2;
#pragma unroll
    for (int o = 16; o; o >>= 1) {
        s += __shfl_down_sync(0xffffffffu, s, o);
        ss += __shfl_down_sync(0xffffffffu, ss, o);
    }
    int w = t >> 5;
    if ((t & 31) == 0) { shs[w] = s; shss[w] = ss; }
    __syncthreads();
    float ts = shs[0] + shs[1] + shs[2] + shs[3];
    float tss = shss[0] + shss[1] + shss[2] + shss[3];
    float mu = ts * (1.f / 384.f);
    float var = tss * (1.f / 384.f) - mu * mu;
    float inv = rsqrtf(var + 1e-5f);

    float h0 = fmaxf((v0 - mu) * inv * __ldg(&g[t])       + __ldg(&b[t]), 0.f);
    float h1 = fmaxf((v1 - mu) * inv * __ldg(&g[t + 128]) + __ldg(&b[t + 128]), 0.f);
    float h2 = fmaxf((v2 - mu) * inv * __ldg(&g[t + 256]) + __ldg(&b[t + 256]), 0.f);
    float p = h0 * __ldg(&lw[t]) + h1 * __ldg(&lw[t + 128]) + h2 * __ldg(&lw[t + 256]);
    __syncthreads();   // shs reuse
#pragma unroll
    for (int o = 16; o; o >>= 1) p += __shfl_down_sync(0xffffffffu, p, o);
    if ((t & 31) == 0) shs[w] = p;
    __syncthreads();
    if (t == 0) {
        float tp = shs[0] + shs[1] + shs[2] + shs[3] + __ldg(&lb[0]);
        dur[row] = expf(fmaxf(tp, 0.f));
    }
}

// ---------------------------------------------------------------------------
// Per-batch inclusive cumsum of target (512 elems), 1 warp per batch row
// ---------------------------------------------------------------------------
__global__ void cumsum_kernel(const int* __restrict__ tgt) {
    int b = blockIdx.x;
    int lane = threadIdx.x;
    const int* tb = tgt + b * LL;
    int v[16];
    int s = 0;
#pragma unroll
    for (int i = 0; i < 16; ++i) { s += tb[lane * 16 + i]; v[i] = s; }
    int incl = s;
#pragma unroll
    for (int o = 1; o < 32; o <<= 1) {
        int n = __shfl_up_sync(0xffffffffu, incl, o);
        if (lane >= o) incl += n;
    }
    int excl = incl - s;
    int* eb = g_ends + b * LL;
#pragma unroll
    for (int i = 0; i < 16; ++i) eb[lane * 16 + i] = v[i] + excl;
}

// ---------------------------------------------------------------------------
// Length-regulator gather: out[b, t, :] = X[b, idx(t), :] * (t < total)
// grid = (BB * 32), each block: 128 t-rows, 256 threads, float4 copies
// ---------------------------------------------------------------------------
__global__ void __launch_bounds__(256)
gather_kernel(const float* __restrict__ X, float* __restrict__ out) {
    __shared__ int se[LL];
    __shared__ int sidx[128];
    int bq = blockIdx.x;
    int b = bq >> 5;
    int t0 = (bq & 31) * 128;
    int tid = threadIdx.x;
    se[tid] = g_ends[b * LL + tid];
    se[tid + 256] = g_ends[b * LL + tid + 256];
    __syncthreads();
    int total = se[LL - 1];
    if (tid < 128) {
        int t = t0 + tid;
        int lo = 0, hi = LL;
        while (lo < hi) {
            int mid = (lo + hi) >> 1;
            if (se[mid] <= t) lo = mid + 1; else hi = mid;
        }
        sidx[tid] = (t < total) ? min(lo, LL - 1) : -1;
    }
    __syncthreads();
    const float4* Xb = (const float4*)(X + (size_t)b * LL * FF);
    float4* Ob = (float4*)(out + (size_t)b * MAX_OUT * FF + (size_t)t0 * FF);
    const int Q = FF / 4;  // 96
#pragma unroll
    for (int it = 0; it < 48; ++it) {
        int lin = it * 256 + tid;
        int r = lin / Q;
        int q = lin - r * Q;
        int idx = sidx[r];
        float4 v = make_float4(0.f, 0.f, 0.f, 0.f);
        if (idx >= 0) v = Xb[idx * Q + q];
        Ob[r * Q + q] = v;
    }
}

// ---------------------------------------------------------------------------
extern "C" void kernel_launch(void* const* d_in, const int* in_sizes, int n_in,
                              void* d_out, int out_size) {
    const float* input = (const float*)d_in[0];
    const int*   target = (const int*)d_in[1];
    const float* w1 = (const float*)d_in[2];
    const float* b1 = (const float*)d_in[3];
    const float* g1 = (const float*)d_in[4];
    const float* be1 = (const float*)d_in[5];
    const float* w2 = (const float*)d_in[6];
    const float* b2 = (const float*)d_in[7];
    const float* g2 = (const float*)d_in[8];
    const float* be2 = (const float*)d_in[9];
    const float* lw = (const float*)d_in[10];
    const float* lb = (const float*)d_in[11];

    float* out = (float*)d_out;
    float* dur = out + ((size_t)out_size - (size_t)BB * LL);

    float *W1t, *W2t, *buf1, *buf2;
    cudaGetSymbolAddress((void**)&W1t, g_W1t);
    cudaGetSymbolAddress((void**)&W2t, g_W2t);
    cudaGetSymbolAddress((void**)&buf1, g_buf1);
    cudaGetSymbolAddress((void**)&buf2, g_buf2);

    // 1. transpose weights
    transpose_w_kernel<<<(KDIM * HH + 255) / 256, 256>>>(w1, w2);
    // 2. conv1 as GEMM (+bias)
    dim3 ggrid(HH / 128, MROWS / 128);
    conv_gemm_kernel<<<ggrid, 256>>>(input, W1t, b1, buf1);
    // 3. LN1 + relu
    ln_relu_kernel<<<MROWS, 128>>>(buf1, g1, be1, buf2);
    // 4. conv2 as GEMM (+bias)
    conv_gemm_kernel<<<ggrid, 256>>>(buf2, W2t, b2, buf1);
    // 5. LN2 + relu + linear + exp -> durations
    ln_dur_kernel<<<MROWS, 128>>>(buf1, g2, be2, lw, lb, dur);
    // 6. cumsum of target
    cumsum_kernel<<<BB, 32>>>(target);
    // 7. length-regulator gather
    gather_kernel<<<BB * 32, 256>>>(input, out);
}

// round 6
// speedup vs baseline: 2.0616x; 2.0616x over previous
#include <cuda_runtime.h>
#include <cuda_bf16.h>
#include <stdint.h>
#include <math.h>

// Problem constants
#define BB 16
#define LL 512
#define FF 384
#define HH 384
#define KW 3
#define MAX_OUT 4096
#define MROWS (BB * LL)        // 8192
#define KDIM (KW * FF)         // 1152

// GEMM tiling
#define BM 128
#define BN 96
#define BK 16
#define NTHREADS 256

// Scratch (static device allocations — allowed)
__device__ __align__(16) __nv_bfloat16 g_W1h[KDIM * HH];
__device__ __align__(16) __nv_bfloat16 g_W1l[KDIM * HH];
__device__ __align__(16) __nv_bfloat16 g_W2h[KDIM * FF];
__device__ __align__(16) __nv_bfloat16 g_W2l[KDIM * FF];
__device__ float g_buf1[MROWS * HH];
__device__ float g_buf2[MROWS * HH];
__device__ int   g_ends[BB * LL];

// ---------------------------------------------------------------------------
// Weight prep: W[h, f, k] (torch Conv1d) -> Wh/Wl[n = h][kk = k*FF + f], bf16
// split: v = hi + lo + O(2^-16 v)
// ---------------------------------------------------------------------------
__global__ void prep_w_kernel(const float* __restrict__ w1,
                              const float* __restrict__ w2) {
    int o = blockIdx.x * 256 + threadIdx.x;
    if (o >= KDIM * HH) return;
    int n = o / KDIM;
    int kk = o - n * KDIM;
    int k = kk / FF;
    int f = kk - k * FF;
    float v1 = w1[(n * FF + f) * KW + k];
    __nv_bfloat16 h1 = __float2bfloat16(v1);
    g_W1h[o] = h1;
    g_W1l[o] = __float2bfloat16(v1 - __bfloat162float(h1));
    float v2 = w2[(n * FF + f) * KW + k];
    __nv_bfloat16 h2 = __float2bfloat16(v2);
    g_W2h[o] = h2;
    g_W2l[o] = __float2bfloat16(v2 - __bfloat162float(h2));
}

// ---------------------------------------------------------------------------
__device__ __forceinline__ void mma16816(float* c,
                                         uint32_t a0, uint32_t a1, uint32_t a2, uint32_t a3,
                                         uint32_t b0, uint32_t b1) {
    asm volatile(
        "mma.sync.aligned.m16n8k16.row.col.f32.bf16.bf16.f32 "
        "{%0,%1,%2,%3}, {%4,%5,%6,%7}, {%8,%9}, {%0,%1,%2,%3};\n"
        : "+f"(c[0]), "+f"(c[1]), "+f"(c[2]), "+f"(c[3])
        : "r"(a0), "r"(a1), "r"(a2), "r"(a3), "r"(b0), "r"(b1));
}

__device__ __forceinline__ uint32_t pack_bf2(__nv_bfloat16 lo, __nv_bfloat16 hi) {
    __nv_bfloat162 t(lo, hi);   // lo -> low 16 bits (col 2t), hi -> high (col 2t+1)
    return *(uint32_t*)&t;
}

__device__ __forceinline__ void cp_async16(uint32_t smem_dst, const void* gsrc) {
    asm volatile("cp.async.cg.shared.global [%0], [%1], 16;\n"
                 :: "r"(smem_dst), "l"(gsrc));
}

// ---------------------------------------------------------------------------
// Implicit-im2col split-bf16 tensor-core GEMM:
//   C[m, n] = sum_kk A(m, kk) * W[n, kk] + bias[n]
//   A(m, kk): m = b*512 + l ; kk = k*384 + f ; value = X[b, l+k-1, f] (0 pad)
// BM=128, BN=96, BK=16, 256 threads, warps 2(m) x 4(n), warp tile 64x24
// C = Ah*Bh + Ah*Bl + Al*Bh  (error ~2^-16)
// ---------------------------------------------------------------------------
__global__ void __launch_bounds__(NTHREADS, 2)
conv_mma_kernel(const float* __restrict__ X,
                const __nv_bfloat16* __restrict__ Wh,
                const __nv_bfloat16* __restrict__ Wl,
                const float* __restrict__ bias,
                float* __restrict__ C) {
    __shared__ __align__(16) uint32_t AsH[2][BM][12];
    __shared__ __align__(16) uint32_t AsL[2][BM][12];
    __shared__ __align__(16) uint32_t BsH[2][BN][12];
    __shared__ __align__(16) uint32_t BsL[2][BN][12];

    const int tid = threadIdx.x;
    const int bn = blockIdx.x * BN;
    const int bm = blockIdx.y * BM;
    const int lane = tid & 31;
    const int warp = tid >> 5;
    const int wm = warp & 1;       // 0..1
    const int wn = warp >> 1;      // 0..3
    const int g = lane >> 2;
    const int tq = lane & 3;

    // A loader mapping: thread -> (row, half)
    const int a_row = tid >> 1;            // 0..127
    const int a_half = tid & 1;            // 0..1 (8 floats each)
    const int a_m = bm + a_row;
    const int a_b = a_m >> 9;
    const int a_l = a_m & (LL - 1);

    float acc[4][3][4];
#pragma unroll
    for (int mt = 0; mt < 4; ++mt)
#pragma unroll
        for (int nt = 0; nt < 3; ++nt)
#pragma unroll
            for (int i = 0; i < 4; ++i) acc[mt][nt][i] = 0.f;

    // ---- helpers as lambdas
    auto load_A = [&](int k0, float4& v0, float4& v1) {
        int kb = k0 / FF;                  // 0..2 (BK chunk never straddles: 384%16==0)
        int f0 = k0 - kb * FF + a_half * 8;
        int lp = a_l + kb - 1;
        if ((unsigned)lp < (unsigned)LL) {
            const float4* p = (const float4*)&X[((a_b << 9) + lp) * FF + f0];
            v0 = p[0];
            v1 = p[1];
        } else {
            v0 = make_float4(0.f, 0.f, 0.f, 0.f);
            v1 = make_float4(0.f, 0.f, 0.f, 0.f);
        }
    };
    auto sts_A = [&](int buf, float4 v0, float4 v1) {
        float f[8] = {v0.x, v0.y, v0.z, v0.w, v1.x, v1.y, v1.z, v1.w};
        uint32_t hw[4], lw[4];
#pragma unroll
        for (int j = 0; j < 4; ++j) {
            __nv_bfloat16 h0 = __float2bfloat16(f[2 * j]);
            __nv_bfloat16 h1 = __float2bfloat16(f[2 * j + 1]);
            __nv_bfloat16 l0 = __float2bfloat16(f[2 * j]     - __bfloat162float(h0));
            __nv_bfloat16 l1 = __float2bfloat16(f[2 * j + 1] - __bfloat162float(h1));
            hw[j] = pack_bf2(h0, h1);
            lw[j] = pack_bf2(l0, l1);
        }
        *(uint4*)&AsH[buf][a_row][a_half * 4] = make_uint4(hw[0], hw[1], hw[2], hw[3]);
        *(uint4*)&AsL[buf][a_row][a_half * 4] = make_uint4(lw[0], lw[1], lw[2], lw[3]);
    };
    auto cp_B = [&](int buf, int k0) {
        if (tid < 192) {
            int n = tid >> 1;
            int chunk = tid & 1;
            size_t goff = (size_t)(bn + n) * KDIM + k0 + chunk * 8;
            uint32_t dH = (uint32_t)__cvta_generic_to_shared(&BsH[buf][n][chunk * 4]);
            uint32_t dL = (uint32_t)__cvta_generic_to_shared(&BsL[buf][n][chunk * 4]);
            cp_async16(dH, Wh + goff);
            cp_async16(dL, Wl + goff);
        }
    };

    // ---- prologue: tile 0
    float4 av0, av1;
    load_A(0, av0, av1);
    cp_B(0, 0);
    asm volatile("cp.async.commit_group;\n");
    sts_A(0, av0, av1);
    asm volatile("cp.async.wait_group 0;\n");
    __syncthreads();

    int buf = 0;
    int k0 = 0;
#pragma unroll 1
    for (int it = 0; it < KDIM / BK; ++it) {
        const bool has_next = (it < KDIM / BK - 1);
        if (has_next) {
            load_A(k0 + BK, av0, av1);
            cp_B(buf ^ 1, k0 + BK);
            asm volatile("cp.async.commit_group;\n");
        }
        // ---- compute on current buffer
        uint32_t bh[3][2], bl[3][2];
#pragma unroll
        for (int nt = 0; nt < 3; ++nt) {
            int n = wn * 24 + nt * 8 + g;
            bh[nt][0] = BsH[buf][n][tq];
            bh[nt][1] = BsH[buf][n][tq + 4];
            bl[nt][0] = BsL[buf][n][tq];
            bl[nt][1] = BsL[buf][n][tq + 4];
        }
#pragma unroll
        for (int mt = 0; mt < 4; ++mt) {
            int r = wm * 64 + mt * 16 + g;
            uint32_t a0 = AsH[buf][r][tq];
            uint32_t a1 = AsH[buf][r + 8][tq];
            uint32_t a2 = AsH[buf][r][tq + 4];
            uint32_t a3 = AsH[buf][r + 8][tq + 4];
#pragma unroll
            for (int nt = 0; nt < 3; ++nt)
                mma16816(acc[mt][nt], a0, a1, a2, a3, bh[nt][0], bh[nt][1]);
#pragma unroll
            for (int nt = 0; nt < 3; ++nt)
                mma16816(acc[mt][nt], a0, a1, a2, a3, bl[nt][0], bl[nt][1]);
            a0 = AsL[buf][r][tq];
            a1 = AsL[buf][r + 8][tq];
            a2 = AsL[buf][r][tq + 4];
            a3 = AsL[buf][r + 8][tq + 4];
#pragma unroll
            for (int nt = 0; nt < 3; ++nt)
                mma16816(acc[mt][nt], a0, a1, a2, a3, bh[nt][0], bh[nt][1]);
        }
        if (has_next) sts_A(buf ^ 1, av0, av1);
        asm volatile("cp.async.wait_group 0;\n");
        __syncthreads();
        buf ^= 1;
        k0 += BK;
    }

    // ---- epilogue: bias + store (float2 per fragment row pair)
#pragma unroll
    for (int nt = 0; nt < 3; ++nt) {
        int col = bn + wn * 24 + nt * 8 + 2 * tq;
        float bx = bias[col], by = bias[col + 1];
#pragma unroll
        for (int mt = 0; mt < 4; ++mt) {
            int row = bm + wm * 64 + mt * 16 + g;
            float2 o0 = make_float2(acc[mt][nt][0] + bx, acc[mt][nt][1] + by);
            float2 o1 = make_float2(acc[mt][nt][2] + bx, acc[mt][nt][3] + by);
            *(float2*)&C[(size_t)row * HH + col] = o0;
            *(float2*)&C[(size_t)(row + 8) * HH + col] = o1;
        }
    }
}

// ---------------------------------------------------------------------------
// LayerNorm(384) + ReLU, one block (128 thr) per row
// ---------------------------------------------------------------------------
__global__ void ln_relu_kernel(const float* __restrict__ X,
                               const float* __restrict__ g,
                               const float* __restrict__ b,
                               float* __restrict__ Y) {
    __shared__ float shs[4], shss[4];
    int row = blockIdx.x;
    int t = threadIdx.x;
    const float* x = X + (size_t)row * 384;
    float v0 = x[t], v1 = x[t + 128], v2 = x[t + 256];
    float s = v0 + v1 + v2;
    float ss = v0 * v0 + v1 * v1 + v2 * v2;
#pragma unroll
    for (int o = 16; o; o >>= 1) {
        s += __shfl_down_sync(0xffffffffu, s, o);
        ss += __shfl_down_sync(0xffffffffu, ss, o);
    }
    int w = t >> 5;
    if ((t & 31) == 0) { shs[w] = s; shss[w] = ss; }
    __syncthreads();
    float ts = shs[0] + shs[1] + shs[2] + shs[3];
    float tss = shss[0] + shss[1] + shss[2] + shss[3];
    float mu = ts * (1.f / 384.f);
    float var = tss * (1.f / 384.f) - mu * mu;
    float inv = rsqrtf(var + 1e-5f);
    float* y = Y + (size_t)row * 384;
    y[t]       = fmaxf((v0 - mu) * inv * __ldg(&g[t])       + __ldg(&b[t]), 0.f);
    y[t + 128] = fmaxf((v1 - mu) * inv * __ldg(&g[t + 128]) + __ldg(&b[t + 128]), 0.f);
    y[t + 256] = fmaxf((v2 - mu) * inv * __ldg(&g[t + 256]) + __ldg(&b[t + 256]), 0.f);
}

// ---------------------------------------------------------------------------
// LayerNorm(384) + ReLU + dot(lin_w) + lin_b + ReLU + exp -> durations[row]
// ---------------------------------------------------------------------------
__global__ void ln_dur_kernel(const float* __restrict__ X,
                              const float* __restrict__ g,
                              const float* __restrict__ b,
                              const float* __restrict__ lw,
                              const float* __restrict__ lb,
                              float* __restrict__ dur) {
    __shared__ float shs[4], shss[4];
    int row = blockIdx.x;
    int t = threadIdx.x;
    const float* x = X + (size_t)row * 384;
    float v0 = x[t], v1 = x[t + 128], v2 = x[t + 256];
    float s = v0 + v1 + v2;
    float ss = v0 * v0 + v1 * v1 + v2 * v2;
#pragma unroll
    for (int o = 16; o; o >>= 1) {
        s += __shfl_down_sync(0xffffffffu, s, o);
        ss += __shfl_down_sync(0xffffffffu, ss, o);
    }
    int w = t >> 5;
    if ((t & 31) == 0) { shs[w] = s; shss[w] = ss; }
    __syncthreads();
    float ts = shs[0] + shs[1] + shs[2] + shs[3];
    float tss = shss[0] + shss[1] + shss[2] + shss[3];
    float mu = ts * (1.f / 384.f);
    float var = tss * (1.f / 384.f) - mu * mu;
    float inv = rsqrtf(var + 1e-5f);

    float h0 = fmaxf((v0 - mu) * inv * __ldg(&g[t])       + __ldg(&b[t]), 0.f);
    float h1 = fmaxf((v1 - mu) * inv * __ldg(&g[t + 128]) + __ldg(&b[t + 128]), 0.f);
    float h2 = fmaxf((v2 - mu) * inv * __ldg(&g[t + 256]) + __ldg(&b[t + 256]), 0.f);
    float p = h0 * __ldg(&lw[t]) + h1 * __ldg(&lw[t + 128]) + h2 * __ldg(&lw[t + 256]);
    __syncthreads();   // shs reuse
#pragma unroll
    for (int o = 16; o; o >>= 1) p += __shfl_down_sync(0xffffffffu, p, o);
    if ((t & 31) == 0) shs[w] = p;
    __syncthreads();
    if (t == 0) {
        float tp = shs[0] + shs[1] + shs[2] + shs[3] + __ldg(&lb[0]);
        dur[row] = expf(fmaxf(tp, 0.f));
    }
}

// ---------------------------------------------------------------------------
// Per-batch inclusive cumsum of target (512 elems), 1 warp per batch row
// ---------------------------------------------------------------------------
__global__ void cumsum_kernel(const int* __restrict__ tgt) {
    int b = blockIdx.x;
    int lane = threadIdx.x;
    const int* tb = tgt + b * LL;
    int v[16];
    int s = 0;
#pragma unroll
    for (int i = 0; i < 16; ++i) { s += tb[lane * 16 + i]; v[i] = s; }
    int incl = s;
#pragma unroll
    for (int o = 1; o < 32; o <<= 1) {
        int n = __shfl_up_sync(0xffffffffu, incl, o);
        if (lane >= o) incl += n;
    }
    int excl = incl - s;
    int* eb = g_ends + b * LL;
#pragma unroll
    for (int i = 0; i < 16; ++i) eb[lane * 16 + i] = v[i] + excl;
}

// ---------------------------------------------------------------------------
// Length-regulator gather: out[b, t, :] = X[b, idx(t), :] * (t < total)
// ---------------------------------------------------------------------------
__global__ void __launch_bounds__(256)
gather_kernel(const float* __restrict__ X, float* __restrict__ out) {
    __shared__ int se[LL];
    __shared__ int sidx[128];
    int bq = blockIdx.x;
    int b = bq >> 5;
    int t0 = (bq & 31) * 128;
    int tid = threadIdx.x;
    se[tid] = g_ends[b * LL + tid];
    se[tid + 256] = g_ends[b * LL + tid + 256];
    __syncthreads();
    int total = se[LL - 1];
    if (tid < 128) {
        int t = t0 + tid;
        int lo = 0, hi = LL;
        while (lo < hi) {
            int mid = (lo + hi) >> 1;
            if (se[mid] <= t) lo = mid + 1; else hi = mid;
        }
        sidx[tid] = (t < total) ? min(lo, LL - 1) : -1;
    }
    __syncthreads();
    const float4* Xb = (const float4*)(X + (size_t)b * LL * FF);
    float4* Ob = (float4*)(out + (size_t)b * MAX_OUT * FF + (size_t)t0 * FF);
    const int Q = FF / 4;  // 96
#pragma unroll
    for (int it = 0; it < 48; ++it) {
        int lin = it * 256 + tid;
        int r = lin / Q;
        int q = lin - r * Q;
        int idx = sidx[r];
        float4 v = make_float4(0.f, 0.f, 0.f, 0.f);
        if (idx >= 0) v = Xb[idx * Q + q];
        Ob[r * Q + q] = v;
    }
}

// ---------------------------------------------------------------------------
extern "C" void kernel_launch(void* const* d_in, const int* in_sizes, int n_in,
                              void* d_out, int out_size) {
    const float* input = (const float*)d_in[0];
    const int*   target = (const int*)d_in[1];
    const float* w1 = (const float*)d_in[2];
    const float* b1 = (const float*)d_in[3];
    const float* g1 = (const float*)d_in[4];
    const float* be1 = (const float*)d_in[5];
    const float* w2 = (const float*)d_in[6];
    const float* b2 = (const float*)d_in[7];
    const float* g2 = (const float*)d_in[8];
    const float* be2 = (const float*)d_in[9];
    const float* lw = (const float*)d_in[10];
    const float* lb = (const float*)d_in[11];

    float* out = (float*)d_out;
    float* dur = out + ((size_t)out_size - (size_t)BB * LL);

    __nv_bfloat16 *W1h, *W1l, *W2h, *W2l;
    float *buf1, *buf2;
    cudaGetSymbolAddress((void**)&W1h, g_W1h);
    cudaGetSymbolAddress((void**)&W1l, g_W1l);
    cudaGetSymbolAddress((void**)&W2h, g_W2h);
    cudaGetSymbolAddress((void**)&W2l, g_W2l);
    cudaGetSymbolAddress((void**)&buf1, g_buf1);
    cudaGetSymbolAddress((void**)&buf2, g_buf2);

    // 1. weight prep (transpose + bf16 hi/lo split)
    prep_w_kernel<<<(KDIM * HH + 255) / 256, 256>>>(w1, w2);
    // 2. conv1 as split-bf16 tensor-core GEMM (+bias)
    dim3 ggrid(HH / BN, MROWS / BM);       // (4, 64) = 256 CTAs
    conv_mma_kernel<<<ggrid, NTHREADS>>>(input, W1h, W1l, b1, buf1);
    // 3. LN1 + relu
    ln_relu_kernel<<<MROWS, 128>>>(buf1, g1, be1, buf2);
    // 4. conv2
    conv_mma_kernel<<<ggrid, NTHREADS>>>(buf2, W2h, W2l, b2, buf1);
    // 5. LN2 + relu + linear + exp -> durations
    ln_dur_kernel<<<MROWS, 128>>>(buf1, g2, be2, lw, lb, dur);
    // 6. cumsum of target
    cumsum_kernel<<<BB, 32>>>(target);
    // 7. length-regulator gather
    gather_kernel<<<BB * 32, 256>>>(input, out);
}

// round 7
// speedup vs baseline: 2.6076x; 1.2648x over previous
#include <cuda_runtime.h>
#include <cuda_bf16.h>
#include <stdint.h>
#include <math.h>

// Problem constants
#define BB 16
#define LL 512
#define FF 384
#define HH 384
#define KW 3
#define MAX_OUT 4096
#define MROWS (BB * LL)        // 8192
#define KDIM (KW * FF)         // 1152

// GEMM tiling
#define BM 128
#define BN 96
#define BK 16
#define NTHREADS 256
#define NTILES (KDIM / BK)     // 72

// Shared-memory layout (dynamic): per stage: A_H | A_L | B_H | B_L
// row stride 48 bytes (16 k-elems * 2B = 32B data + 16B pad) -> conflict-free ldmatrix
#define ROWB 48
#define A_SZ (BM * ROWB)               // 6144
#define B_SZ (BN * ROWB)               // 4608
#define STAGE_SZ (2 * A_SZ + 2 * B_SZ) // 21504
#define NSTAGES 3
#define SMEM_BYTES (NSTAGES * STAGE_SZ) // 64512

// Scratch (static device allocations — allowed)
__device__ __align__(16) __nv_bfloat16 g_W1h[KDIM * HH];
__device__ __align__(16) __nv_bfloat16 g_W1l[KDIM * HH];
__device__ __align__(16) __nv_bfloat16 g_W2h[KDIM * FF];
__device__ __align__(16) __nv_bfloat16 g_W2l[KDIM * FF];
__device__ __align__(16) __nv_bfloat16 g_Xh[MROWS * FF];
__device__ __align__(16) __nv_bfloat16 g_Xl[MROWS * FF];
__device__ __align__(16) __nv_bfloat16 g_Yh[MROWS * HH];
__device__ __align__(16) __nv_bfloat16 g_Yl[MROWS * HH];
__device__ float g_buf1[MROWS * HH];
__device__ int   g_ends[BB * LL];

// ---------------------------------------------------------------------------
// Weight prep: W[h, f, k] (torch Conv1d) -> Wh/Wl[n][kk = k*FF + f], bf16 split
// ---------------------------------------------------------------------------
__global__ void prep_w_kernel(const float* __restrict__ w1,
                              const float* __restrict__ w2) {
    int o = blockIdx.x * 256 + threadIdx.x;
    if (o >= KDIM * HH) return;
    int n = o / KDIM;
    int kk = o - n * KDIM;
    int k = kk / FF;
    int f = kk - k * FF;
    float v1 = w1[(n * FF + f) * KW + k];
    __nv_bfloat16 h1 = __float2bfloat16(v1);
    g_W1h[o] = h1;
    g_W1l[o] = __float2bfloat16(v1 - __bfloat162float(h1));
    float v2 = w2[(n * FF + f) * KW + k];
    __nv_bfloat16 h2 = __float2bfloat16(v2);
    g_W2h[o] = h2;
    g_W2l[o] = __float2bfloat16(v2 - __bfloat162float(h2));
}

// ---------------------------------------------------------------------------
// Input split: X fp32 -> Xh + Xl bf16 (4 elems per thread)
// ---------------------------------------------------------------------------
__global__ void split_input_kernel(const float* __restrict__ X) {
    int i = blockIdx.x * 256 + threadIdx.x;       // index of float4
    if (i >= MROWS * FF / 4) return;
    float4 v = ((const float4*)X)[i];
    float f[4] = {v.x, v.y, v.z, v.w};
    __nv_bfloat162 h2[2], l2[2];
#pragma unroll
    for (int j = 0; j < 2; ++j) {
        __nv_bfloat16 h0 = __float2bfloat16(f[2 * j]);
        __nv_bfloat16 h1 = __float2bfloat16(f[2 * j + 1]);
        h2[j] = __nv_bfloat162(h0, h1);
        l2[j] = __nv_bfloat162(__float2bfloat16(f[2 * j]     - __bfloat162float(h0)),
                               __float2bfloat16(f[2 * j + 1] - __bfloat162float(h1)));
    }
    ((__nv_bfloat162*)g_Xh)[2 * i]     = h2[0];
    ((__nv_bfloat162*)g_Xh)[2 * i + 1] = h2[1];
    ((__nv_bfloat162*)g_Xl)[2 * i]     = l2[0];
    ((__nv_bfloat162*)g_Xl)[2 * i + 1] = l2[1];
}

// ---------------------------------------------------------------------------
__device__ __forceinline__ void mma16816(float* c,
                                         uint32_t a0, uint32_t a1, uint32_t a2, uint32_t a3,
                                         uint32_t b0, uint32_t b1) {
    asm volatile(
        "mma.sync.aligned.m16n8k16.row.col.f32.bf16.bf16.f32 "
        "{%0,%1,%2,%3}, {%4,%5,%6,%7}, {%8,%9}, {%0,%1,%2,%3};\n"
        : "+f"(c[0]), "+f"(c[1]), "+f"(c[2]), "+f"(c[3])
        : "r"(a0), "r"(a1), "r"(a2), "r"(a3), "r"(b0), "r"(b1));
}

__device__ __forceinline__ void cp16(uint32_t dst, const void* src) {
    asm volatile("cp.async.cg.shared.global [%0], [%1], 16;\n"
                 :: "r"(dst), "l"(src));
}
__device__ __forceinline__ void cp16z(uint32_t dst, const void* src, int srcbytes) {
    asm volatile("cp.async.cg.shared.global [%0], [%1], 16, %2;\n"
                 :: "r"(dst), "l"(src), "r"(srcbytes));
}
__device__ __forceinline__ void ldsm_x4(uint32_t& r0, uint32_t& r1, uint32_t& r2, uint32_t& r3,
                                        uint32_t addr) {
    asm volatile("ldmatrix.sync.aligned.m8n8.x4.shared.b16 {%0,%1,%2,%3}, [%4];\n"
                 : "=r"(r0), "=r"(r1), "=r"(r2), "=r"(r3) : "r"(addr));
}
__device__ __forceinline__ void ldsm_x2(uint32_t& r0, uint32_t& r1, uint32_t addr) {
    asm volatile("ldmatrix.sync.aligned.m8n8.x2.shared.b16 {%0,%1}, [%2];\n"
                 : "=r"(r0), "=r"(r1) : "r"(addr));
}

// ---------------------------------------------------------------------------
// Implicit-im2col split-bf16 tensor-core GEMM, all-cp.async 3-stage pipeline:
//   C[m, n] = sum_kk A(m, kk) * W[n, kk] + bias[n]
//   A(m, kk): m = b*512 + l ; kk = kb*384 + f ; value = Xs[b, l+kb-1, f] (0 pad)
// C = Ah*Bh + Ah*Bl + Al*Bh  (error ~2^-16)
// ---------------------------------------------------------------------------
__global__ void __launch_bounds__(NTHREADS, 2)
conv_mma_kernel(const __nv_bfloat16* __restrict__ Xh,
                const __nv_bfloat16* __restrict__ Xl,
                const __nv_bfloat16* __restrict__ Wh,
                const __nv_bfloat16* __restrict__ Wl,
                const float* __restrict__ bias,
                float* __restrict__ C) {
    extern __shared__ char smem[];
    const uint32_t sb = (uint32_t)__cvta_generic_to_shared(smem);

    const int tid = threadIdx.x;
    const int bn = blockIdx.x * BN;
    const int bm = blockIdx.y * BM;
    const int lane = tid & 31;
    const int warp = tid >> 5;
    const int wm = warp & 1;       // 0..1 (m)
    const int wn = warp >> 1;      // 0..3 (n)
    const int g = lane >> 2;
    const int tq = lane & 3;

    // --- loader thread mapping
    const int a_row = tid >> 1;            // 0..127
    const int a_ck = tid & 1;              // 16B chunk within 32B row slice
    const int a_m = bm + a_row;
    const int a_b = a_m >> 9;
    const int a_l = a_m & (LL - 1);
    const uint32_t dstA = sb + a_row * ROWB + a_ck * 16;
    const int b_row = a_row;               // reuse for tid<192
    const uint32_t dstB = sb + 2 * A_SZ + b_row * ROWB + a_ck * 16;

    // --- ldmatrix lane offsets
    const uint32_t offA = (uint32_t)((wm * 64 + ((lane >> 3) & 1) * 8 + (lane & 7)) * ROWB
                                     + (lane >> 4) * 16);
    const uint32_t offB4 = (uint32_t)((wn * 24 + ((lane >> 4) & 1) * 8 + (lane & 7)) * ROWB
                                      + ((lane >> 3) & 1) * 16);
    const int ln2 = lane & 15;
    const uint32_t offB2 = (uint32_t)((wn * 24 + 16 + (ln2 & 7)) * ROWB
                                      + ((ln2 >> 3) & 1) * 16);

    float acc[4][3][4];
#pragma unroll
    for (int mt = 0; mt < 4; ++mt)
#pragma unroll
        for (int nt = 0; nt < 3; ++nt)
#pragma unroll
            for (int i = 0; i < 4; ++i) acc[mt][nt][i] = 0.f;

    auto load_tile = [&](int stage, int it) {
        int kb = it / 24;                   // 0..2
        int f0 = (it - kb * 24) * 16;
        // A (hi + lo)
        int lp = a_l + kb - 1;
        int valid = ((unsigned)lp < (unsigned)LL) ? 16 : 0;
        int grow = (a_b << 9) + max(0, min(lp, LL - 1));
        size_t aoff = (size_t)grow * FF + f0 + a_ck * 8;
        uint32_t dA = dstA + stage * STAGE_SZ;
        cp16z(dA, Xh + aoff, valid);
        cp16z(dA + A_SZ, Xl + aoff, valid);
        // B (hi + lo)
        if (tid < 192) {
            size_t boff = (size_t)(bn + b_row) * KDIM + kb * FF + f0 + a_ck * 8;
            uint32_t dB = dstB + stage * STAGE_SZ;
            cp16(dB, Wh + boff);
            cp16(dB + B_SZ, Wl + boff);
        }
        asm volatile("cp.async.commit_group;\n");
    };

    // prologue: stages 0,1
    load_tile(0, 0);
    load_tile(1, 1);

    int stage = 0;
#pragma unroll 1
    for (int it = 0; it < NTILES; ++it) {
        asm volatile("cp.async.wait_group 1;\n");
        __syncthreads();
        // prefetch tile it+2 into the stage last read at it-1 (safe after barrier)
        if (it + 2 < NTILES) {
            int s2 = stage + 2; if (s2 >= NSTAGES) s2 -= NSTAGES;
            load_tile(s2, it + 2);
        } else {
            asm volatile("cp.async.commit_group;\n");
        }
        // ---- compute on 'stage'
        const uint32_t base = sb + stage * STAGE_SZ;
        uint32_t bh[3][2], bl[3][2];
        ldsm_x4(bh[0][0], bh[0][1], bh[1][0], bh[1][1], base + 2 * A_SZ + offB4);
        ldsm_x2(bh[2][0], bh[2][1], base + 2 * A_SZ + offB2);
        ldsm_x4(bl[0][0], bl[0][1], bl[1][0], bl[1][1], base + 2 * A_SZ + B_SZ + offB4);
        ldsm_x2(bl[2][0], bl[2][1], base + 2 * A_SZ + B_SZ + offB2);
#pragma unroll
        for (int mt = 0; mt < 4; ++mt) {
            uint32_t aH[4], aL[4];
            ldsm_x4(aH[0], aH[1], aH[2], aH[3], base + offA + mt * 16 * ROWB);
            ldsm_x4(aL[0], aL[1], aL[2], aL[3], base + A_SZ + offA + mt * 16 * ROWB);
#pragma unroll
            for (int nt = 0; nt < 3; ++nt)
                mma16816(acc[mt][nt], aH[0], aH[1], aH[2], aH[3], bh[nt][0], bh[nt][1]);
#pragma unroll
            for (int nt = 0; nt < 3; ++nt)
                mma16816(acc[mt][nt], aH[0], aH[1], aH[2], aH[3], bl[nt][0], bl[nt][1]);
#pragma unroll
            for (int nt = 0; nt < 3; ++nt)
                mma16816(acc[mt][nt], aL[0], aL[1], aL[2], aL[3], bh[nt][0], bh[nt][1]);
        }
        ++stage; if (stage >= NSTAGES) stage = 0;
    }

    // ---- epilogue: bias + store
#pragma unroll
    for (int nt = 0; nt < 3; ++nt) {
        int col = bn + wn * 24 + nt * 8 + 2 * tq;
        float bx = __ldg(&bias[col]), by = __ldg(&bias[col + 1]);
#pragma unroll
        for (int mt = 0; mt < 4; ++mt) {
            int row = bm + wm * 64 + mt * 16 + g;
            float2 o0 = make_float2(acc[mt][nt][0] + bx, acc[mt][nt][1] + by);
            float2 o1 = make_float2(acc[mt][nt][2] + bx, acc[mt][nt][3] + by);
            *(float2*)&C[(size_t)row * HH + col] = o0;
            *(float2*)&C[(size_t)(row + 8) * HH + col] = o1;
        }
    }
}

// ---------------------------------------------------------------------------
// LayerNorm(384) + ReLU -> bf16 hi/lo split outputs (for next GEMM)
// ---------------------------------------------------------------------------
__global__ void ln_relu_split_kernel(const float* __restrict__ X,
                                     const float* __restrict__ g,
                                     const float* __restrict__ b) {
    __shared__ float shs[4], shss[4];
    int row = blockIdx.x;
    int t = threadIdx.x;
    const float* x = X + (size_t)row * 384;
    float v0 = x[t], v1 = x[t + 128], v2 = x[t + 256];
    float s = v0 + v1 + v2;
    float ss = v0 * v0 + v1 * v1 + v2 * v2;
#pragma unroll
    for (int o = 16; o; o >>= 1) {
        s += __shfl_down_sync(0xffffffffu, s, o);
        ss += __shfl_down_sync(0xffffffffu, ss, o);
    }
    int w = t >> 5;
    if ((t & 31) == 0) { shs[w] = s; shss[w] = ss; }
    __syncthreads();
    float ts = shs[0] + shs[1] + shs[2] + shs[3];
    float tss = shss[0] + shss[1] + shss[2] + shss[3];
    float mu = ts * (1.f / 384.f);
    float var = tss * (1.f / 384.f) - mu * mu;
    float inv = rsqrtf(var + 1e-5f);
#pragma unroll
    for (int j = 0; j < 3; ++j) {
        int c = t + j * 128;
        float v = (j == 0) ? v0 : (j == 1) ? v1 : v2;
        float y = fmaxf((v - mu) * inv * __ldg(&g[c]) + __ldg(&b[c]), 0.f);
        __nv_bfloat16 h = __float2bfloat16(y);
        g_Yh[(size_t)row * 384 + c] = h;
        g_Yl[(size_t)row * 384 + c] = __float2bfloat16(y - __bfloat162float(h));
    }
}

// ---------------------------------------------------------------------------
// LayerNorm(384) + ReLU + dot(lin_w) + lin_b + ReLU + exp -> durations[row]
// ---------------------------------------------------------------------------
__global__ void ln_dur_kernel(const float* __restrict__ X,
                              const float* __restrict__ g,
                              const float* __restrict__ b,
                              const float* __restrict__ lw,
                              const float* __restrict__ lb,
                              float* __restrict__ dur) {
    __shared__ float shs[4], shss[4];
    int row = blockIdx.x;
    int t = threadIdx.x;
    const float* x = X + (size_t)row * 384;
    float v0 = x[t], v1 = x[t + 128], v2 = x[t + 256];
    float s = v0 + v1 + v2;
    float ss = v0 * v0 + v1 * v1 + v2 * v2;
#pragma unroll
    for (int o = 16; o; o >>= 1) {
        s += __shfl_down_sync(0xffffffffu, s, o);
        ss += __shfl_down_sync(0xffffffffu, ss, o);
    }
    int w = t >> 5;
    if ((t & 31) == 0) { shs[w] = s; shss[w] = ss; }
    __syncthreads();
    float ts = shs[0] + shs[1] + shs[2] + shs[3];
    float tss = shss[0] + shss[1] + shss[2] + shss[3];
    float mu = ts * (1.f / 384.f);
    float var = tss * (1.f / 384.f) - mu * mu;
    float inv = rsqrtf(var + 1e-5f);

    float h0 = fmaxf((v0 - mu) * inv * __ldg(&g[t])       + __ldg(&b[t]), 0.f);
    float h1 = fmaxf((v1 - mu) * inv * __ldg(&g[t + 128]) + __ldg(&b[t + 128]), 0.f);
    float h2 = fmaxf((v2 - mu) * inv * __ldg(&g[t + 256]) + __ldg(&b[t + 256]), 0.f);
    float p = h0 * __ldg(&lw[t]) + h1 * __ldg(&lw[t + 128]) + h2 * __ldg(&lw[t + 256]);
    __syncthreads();   // shs reuse
#pragma unroll
    for (int o = 16; o; o >>= 1) p += __shfl_down_sync(0xffffffffu, p, o);
    if ((t & 31) == 0) shs[w] = p;
    __syncthreads();
    if (t == 0) {
        float tp = shs[0] + shs[1] + shs[2] + shs[3] + __ldg(&lb[0]);
        dur[row] = expf(fmaxf(tp, 0.f));
    }
}

// ---------------------------------------------------------------------------
// Per-batch inclusive cumsum of target (512 elems), 1 warp per batch row
// ---------------------------------------------------------------------------
__global__ void cumsum_kernel(const int* __restrict__ tgt) {
    int b = blockIdx.x;
    int lane = threadIdx.x;
    const int* tb = tgt + b * LL;
    int v[16];
    int s = 0;
#pragma unroll
    for (int i = 0; i < 16; ++i) { s += tb[lane * 16 + i]; v[i] = s; }
    int incl = s;
#pragma unroll
    for (int o = 1; o < 32; o <<= 1) {
        int n = __shfl_up_sync(0xffffffffu, incl, o);
        if (lane >= o) incl += n;
    }
    int excl = incl - s;
    int* eb = g_ends + b * LL;
#pragma unroll
    for (int i = 0; i < 16; ++i) eb[lane * 16 + i] = v[i] + excl;
}

// ---------------------------------------------------------------------------
// Length-regulator gather: out[b, t, :] = X[b, idx(t), :] * (t < total)
// ---------------------------------------------------------------------------
__global__ void __launch_bounds__(256)
gather_kernel(const float* __restrict__ X, float* __restrict__ out) {
    __shared__ int se[LL];
    __shared__ int sidx[128];
    int bq = blockIdx.x;
    int b = bq >> 5;
    int t0 = (bq & 31) * 128;
    int tid = threadIdx.x;
    se[tid] = g_ends[b * LL + tid];
    se[tid + 256] = g_ends[b * LL + tid + 256];
    __syncthreads();
    int total = se[LL - 1];
    if (tid < 128) {
        int t = t0 + tid;
        int lo = 0, hi = LL;
        while (lo < hi) {
            int mid = (lo + hi) >> 1;
            if (se[mid] <= t) lo = mid + 1; else hi = mid;
        }
        sidx[tid] = (t < total) ? min(lo, LL - 1) : -1;
    }
    __syncthreads();
    const float4* Xb = (const float4*)(X + (size_t)b * LL * FF);
    float4* Ob = (float4*)(out + (size_t)b * MAX_OUT * FF + (size_t)t0 * FF);
    const int Q = FF / 4;  // 96
#pragma unroll
    for (int it = 0; it < 48; ++it) {
        int lin = it * 256 + tid;
        int r = lin / Q;
        int q = lin - r * Q;
        int idx = sidx[r];
        float4 v = make_float4(0.f, 0.f, 0.f, 0.f);
        if (idx >= 0) v = Xb[idx * Q + q];
        Ob[r * Q + q] = v;
    }
}

// ---------------------------------------------------------------------------
extern "C" void kernel_launch(void* const* d_in, const int* in_sizes, int n_in,
                              void* d_out, int out_size) {
    const float* input = (const float*)d_in[0];
    const int*   target = (const int*)d_in[1];
    const float* w1 = (const float*)d_in[2];
    const float* b1 = (const float*)d_in[3];
    const float* g1 = (const float*)d_in[4];
    const float* be1 = (const float*)d_in[5];
    const float* w2 = (const float*)d_in[6];
    const float* b2 = (const float*)d_in[7];
    const float* g2 = (const float*)d_in[8];
    const float* be2 = (const float*)d_in[9];
    const float* lw = (const float*)d_in[10];
    const float* lb = (const float*)d_in[11];

    float* out = (float*)d_out;
    float* dur = out + ((size_t)out_size - (size_t)BB * LL);

    __nv_bfloat16 *W1h, *W1l, *W2h, *W2l, *Xh, *Xl, *Yh, *Yl;
    float* buf1;
    cudaGetSymbolAddress((void**)&W1h, g_W1h);
    cudaGetSymbolAddress((void**)&W1l, g_W1l);
    cudaGetSymbolAddress((void**)&W2h, g_W2h);
    cudaGetSymbolAddress((void**)&W2l, g_W2l);
    cudaGetSymbolAddress((void**)&Xh, g_Xh);
    cudaGetSymbolAddress((void**)&Xl, g_Xl);
    cudaGetSymbolAddress((void**)&Yh, g_Yh);
    cudaGetSymbolAddress((void**)&Yl, g_Yl);
    cudaGetSymbolAddress((void**)&buf1, g_buf1);

    static int smem_set = 0;
    cudaFuncSetAttribute(conv_mma_kernel,
                         cudaFuncAttributeMaxDynamicSharedMemorySize, SMEM_BYTES);
    (void)smem_set;

    // 1. weight prep + input split
    prep_w_kernel<<<(KDIM * HH + 255) / 256, 256>>>(w1, w2);
    split_input_kernel<<<(MROWS * FF / 4 + 255) / 256, 256>>>(input);
    // 2. conv1 as split-bf16 tensor-core GEMM (+bias)
    dim3 ggrid(HH / BN, MROWS / BM);       // (4, 64) = 256 CTAs
    conv_mma_kernel<<<ggrid, NTHREADS, SMEM_BYTES>>>(Xh, Xl, W1h, W1l, b1, buf1);
    // 3. LN1 + relu -> bf16 split
    ln_relu_split_kernel<<<MROWS, 128>>>(buf1, g1, be1);
    // 4. conv2
    conv_mma_kernel<<<ggrid, NTHREADS, SMEM_BYTES>>>(Yh, Yl, W2h, W2l, b2, buf1);
    // 5. LN2 + relu + linear + exp -> durations
    ln_dur_kernel<<<MROWS, 128>>>(buf1, g2, be2, lw, lb, dur);
    // 6. cumsum of target
    cumsum_kernel<<<BB, 32>>>(target);
    // 7. length-regulator gather
    gather_kernel<<<BB * 32, 256>>>(input, out);
}